// round 1
// baseline (speedup 1.0000x reference)
#include <cuda_runtime.h>
#include <cuda_bf16.h>
#include <math.h>

// ---------------- problem constants ----------------
#define NB    16
#define LSEQ  128
#define DH    768
#define MSP   8
#define HH    8
#define JR    30
#define RR    49
#define IMGD  2048
#define NM    128            // NB*MSP
#define ROWS  3840           // NM*JR
#define NR    784            // NB*RR

// ---------------- scratch (device globals; no cudaMalloc allowed) ----------------
__device__ float g_C1[NR * DH];                 // res_feature
__device__ float g_Bqk[HH * DH * DH];           // Wq_h @ Wk_h^T
__device__ float g_Wvf[HH * DH * DH];           // Wv_h @ Wfc_h
__device__ float g_KC[HH * NR * DH];            // C1 @ Bqk_h^T
__device__ float g_VC[HH * NR * DH];            // C1 @ Wvf_h
__device__ float g_span[ROWS * DH];             // gathered span embeddings
__device__ float g_att[ROWS * DH];              // MHA out (+res, then LN in-place)
__device__ float g_P[NM * HH * JR * RR];        // attention probabilities
__device__ float g_cat[ROWS * 2 * DH];          // concat(span, att)
__device__ float g_f1[ROWS * 2 * DH];           // tanh(cat @ Wa1 + b)
__device__ float g_fused[ROWS * DH];            // f1 @ Wa2 + b
__device__ float g_pool[NM * DH];
__device__ float g_hid[NM * DH];

// ---------------- generic tiled SGEMM ----------------
// C[M,N] = act( A[M,K] @ (TRANSB ? B[N,K]^T : B[K,N]) + bias )
// 128x128 tile, BK=16, 256 threads, 8x8 per thread. N must be a multiple of 128.
// Batched over blockIdx.z via element strides sA/sB/sC.
template<bool TRANSB, bool BIAS, bool TANH_ACT>
__global__ void sgemm(const float* __restrict__ A, int lda, long sA,
                      const float* __restrict__ B, int ldb, long sB,
                      float* __restrict__ C, int ldc, long sC,
                      const float* __restrict__ bias,
                      int M, int N, int K)
{
    A += (long)blockIdx.z * sA;
    B += (long)blockIdx.z * sB;
    C += (long)blockIdx.z * sC;

    __shared__ float As[16][128];
    __shared__ float Bs[16][128];

    const int tid = threadIdx.x;
    const int m0 = blockIdx.y * 128;
    const int n0 = blockIdx.x * 128;
    const int tx = tid & 15;    // 16 col-groups
    const int ty = tid >> 4;    // 16 row-groups

    float acc[8][8];
#pragma unroll
    for (int i = 0; i < 8; i++)
#pragma unroll
        for (int j = 0; j < 8; j++) acc[i][j] = 0.f;

    for (int k0 = 0; k0 < K; k0 += 16) {
        // A tile: 128 rows x 16 k, as 512 float4 (4 k per float4)
#pragma unroll
        for (int i = 0; i < 2; i++) {
            int li = tid + i * 256;
            int row = li >> 2;
            int kk  = (li & 3) << 2;
            float4 v = make_float4(0.f, 0.f, 0.f, 0.f);
            if (m0 + row < M)
                v = *reinterpret_cast<const float4*>(&A[(long)(m0 + row) * lda + k0 + kk]);
            As[kk + 0][row] = v.x; As[kk + 1][row] = v.y;
            As[kk + 2][row] = v.z; As[kk + 3][row] = v.w;
        }
        if (!TRANSB) {
#pragma unroll
            for (int i = 0; i < 2; i++) {
                int li = tid + i * 256;
                int kr = li >> 5;             // 0..15
                int nn = (li & 31) << 2;      // 0..124
                float4 v = *reinterpret_cast<const float4*>(&B[(long)(k0 + kr) * ldb + n0 + nn]);
                *reinterpret_cast<float4*>(&Bs[kr][nn]) = v;
            }
        } else {
#pragma unroll
            for (int i = 0; i < 2; i++) {
                int li = tid + i * 256;
                int nr = li >> 2;
                int kk = (li & 3) << 2;
                float4 v = make_float4(0.f, 0.f, 0.f, 0.f);
                if (n0 + nr < N)
                    v = *reinterpret_cast<const float4*>(&B[(long)(n0 + nr) * ldb + k0 + kk]);
                Bs[kk + 0][nr] = v.x; Bs[kk + 1][nr] = v.y;
                Bs[kk + 2][nr] = v.z; Bs[kk + 3][nr] = v.w;
            }
        }
        __syncthreads();

#pragma unroll
        for (int k = 0; k < 16; k++) {
            float a[8], b[8];
#pragma unroll
            for (int i = 0; i < 8; i++) a[i] = As[k][ty * 8 + i];
#pragma unroll
            for (int j = 0; j < 8; j++) b[j] = Bs[k][tx * 8 + j];
#pragma unroll
            for (int i = 0; i < 8; i++)
#pragma unroll
                for (int j = 0; j < 8; j++) acc[i][j] += a[i] * b[j];
        }
        __syncthreads();
    }

#pragma unroll
    for (int i = 0; i < 8; i++) {
        int m = m0 + ty * 8 + i;
        if (m >= M) continue;
#pragma unroll
        for (int j = 0; j < 8; j++) {
            int n = n0 + tx * 8 + j;
            float v = acc[i][j];
            if (BIAS) v += bias[n];
            if (TANH_ACT) v = tanhf(v);
            C[(long)m * ldc + n] = v;
        }
    }
}

// ---------------- span gather ----------------
__global__ void gather_kernel(const float* __restrict__ seq, const int* __restrict__ starts)
{
    int row = blockIdx.x;             // 0..3839
    int sp = row / JR, j = row - sp * JR;
    int n = sp >> 3;
    int start = starts[sp] + n * LSEQ;
    int tok = start + j;
    if (tok > NB * LSEQ - 1) tok = NB * LSEQ - 1;
    const float4* src = reinterpret_cast<const float4*>(seq + (long)tok * DH);
    float4* dst = reinterpret_cast<float4*>(g_span + (long)row * DH);
    int t = threadIdx.x;
    if (t < DH / 4) dst[t] = src[t];
}

// ---------------- attention scores + softmax (per span, head) ----------------
__global__ void att_scores_kernel()
{
    const int h = blockIdx.x, s = blockIdx.y;
    const int b = s >> 3;
    __shared__ float sQ[JR][129];
    __shared__ float sK[RR][129];
    __shared__ float sS[JR * RR];
    const int t = threadIdx.x;
    const int q = t % JR, rg = t / JR;       // active: t < 240

    int rr[7];
#pragma unroll
    for (int i = 0; i < 7; i++) { int r = rg + i * 8; rr[i] = (r < RR) ? r : 0; }

    float acc[7];
#pragma unroll
    for (int i = 0; i < 7; i++) acc[i] = 0.f;

    const float* Qp = g_span + (long)s * JR * DH;
    const float* Kp = g_KC + ((long)h * NR + (long)b * RR) * DH;

    for (int k0 = 0; k0 < DH; k0 += 128) {
        for (int e = t; e < JR * 128; e += 256)
            sQ[e >> 7][e & 127] = Qp[(long)(e >> 7) * DH + k0 + (e & 127)];
        for (int e = t; e < RR * 128; e += 256)
            sK[e >> 7][e & 127] = Kp[(long)(e >> 7) * DH + k0 + (e & 127)];
        __syncthreads();
        if (t < 240) {
            for (int kk = 0; kk < 128; kk++) {
                float a = sQ[q][kk];
#pragma unroll
                for (int i = 0; i < 7; i++) acc[i] += a * sK[rr[i]][kk];
            }
        }
        __syncthreads();
    }

    const float scale = 1.0f / sqrtf((float)DH);
    if (t < 240) {
#pragma unroll
        for (int i = 0; i < 7; i++) {
            int r = rg + i * 8;
            if (r < RR) sS[q * RR + r] = acc[i] * scale;
        }
    }
    __syncthreads();

    if (t < JR) {
        float* row = sS + t * RR;
        float mx = row[0];
        for (int r = 1; r < RR; r++) mx = fmaxf(mx, row[r]);
        float sum = 0.f;
        for (int r = 0; r < RR; r++) { float e = expf(row[r] - mx); row[r] = e; sum += e; }
        float inv = 1.f / sum;
        float* out = g_P + (((long)s * HH + h) * JR + t) * RR;
        for (int r = 0; r < RR; r++) out[r] = row[r] * inv;
    }
}

// ---------------- out = sum_h P_h @ VC_h + residual (per span) ----------------
__global__ void att_out_kernel()
{
    const int s = blockIdx.x, b = s >> 3, t = threadIdx.x;
    __shared__ float sP[HH * JR * RR];      // 11760 floats
    for (int e = t; e < HH * JR * RR; e += 256)
        sP[e] = g_P[(long)s * HH * JR * RR + e];
    __syncthreads();

    for (int dc = 0; dc < 3; dc++) {
        int d = dc * 256 + t;
        float acc[JR];
#pragma unroll
        for (int q = 0; q < JR; q++) acc[q] = 0.f;
        for (int h = 0; h < HH; h++) {
            const float* V = g_VC + ((long)h * NR + (long)b * RR) * DH + d;
            const float* P = sP + h * JR * RR;
            for (int r = 0; r < RR; r++) {
                float v = V[(long)r * DH];
#pragma unroll
                for (int q = 0; q < JR; q++) acc[q] += P[q * RR + r] * v;
            }
        }
        for (int q = 0; q < JR; q++) {
            long idx = ((long)s * JR + q) * DH + d;
            g_att[idx] = acc[q] + g_span[idx];
        }
    }
}

// ---------------- layernorm (in place on g_att) ----------------
__global__ void ln_kernel(const float* __restrict__ gam, const float* __restrict__ bet)
{
    int row = blockIdx.x, t = threadIdx.x;
    float* x = g_att + (long)row * DH;
    float v0 = x[t], v1 = x[t + 256], v2 = x[t + 512];
    __shared__ float red[256];
    red[t] = v0 + v1 + v2;
    __syncthreads();
    for (int o = 128; o > 0; o >>= 1) { if (t < o) red[t] += red[t + o]; __syncthreads(); }
    float mu = red[0] * (1.f / DH);
    __syncthreads();
    float d0 = v0 - mu, d1 = v1 - mu, d2 = v2 - mu;
    red[t] = d0 * d0 + d1 * d1 + d2 * d2;
    __syncthreads();
    for (int o = 128; o > 0; o >>= 1) { if (t < o) red[t] += red[t + o]; __syncthreads(); }
    float rstd = rsqrtf(red[0] * (1.f / DH) + 1e-5f);
    x[t]       = d0 * rstd * gam[t]       + bet[t];
    x[t + 256] = d1 * rstd * gam[t + 256] + bet[t + 256];
    x[t + 512] = d2 * rstd * gam[t + 512] + bet[t + 512];
}

// ---------------- concat(span, att) ----------------
__global__ void concat_kernel()
{
    int row = blockIdx.x, t = threadIdx.x;
    const float4* a = reinterpret_cast<const float4*>(g_span + (long)row * DH);
    const float4* c = reinterpret_cast<const float4*>(g_att + (long)row * DH);
    float4* o = reinterpret_cast<float4*>(g_cat + (long)row * 2 * DH);
    if (t < DH / 4) { o[t] = a[t]; o[DH / 4 + t] = c[t]; }
}

// ---------------- unary score + masked softmax pooling ----------------
__global__ void pool_kernel(const float* __restrict__ W_un, const float* __restrict__ b_un,
                            const int* __restrict__ starts, const int* __restrict__ ends)
{
    int sp = blockIdx.x, t = threadIdx.x;
    int lane = t & 31, w = t >> 5;
    __shared__ float sS[JR];
    __shared__ float sProb[JR];

    for (int j = w; j < JR; j += 8) {
        const float* fr = g_fused + ((long)sp * JR + j) * DH;
        float acc = 0.f;
        for (int k = lane; k < DH; k += 32) acc += fr[k] * W_un[k];
        for (int o = 16; o; o >>= 1) acc += __shfl_xor_sync(0xffffffffu, acc, o);
        if (lane == 0) sS[j] = acc + b_un[0];
    }
    __syncthreads();
    if (t == 0) {
        int width = ends[sp] - starts[sp] + 1;
        float mx = -1e30f;
        for (int j = 0; j < JR; j++) {
            float v = sS[j] + ((j < width) ? 0.f : -10000.f);
            sS[j] = v; mx = fmaxf(mx, v);
        }
        float sum = 0.f;
        for (int j = 0; j < JR; j++) { float e = expf(sS[j] - mx); sProb[j] = e; sum += e; }
        float inv = 1.f / sum;
        for (int j = 0; j < JR; j++) sProb[j] *= inv;
    }
    __syncthreads();
    for (int d = t; d < DH; d += 256) {
        float acc = 0.f;
        for (int j = 0; j < JR; j++) acc += sProb[j] * g_fused[((long)sp * JR + j) * DH + d];
        g_pool[(long)sp * DH + d] = acc;
    }
}

// ---------------- classifier ----------------
__global__ void cls_kernel(const float* __restrict__ W_cls, const float* __restrict__ b_cls,
                           float* __restrict__ out)
{
    int row = blockIdx.x, t = threadIdx.x;
    int lane = t & 31, c = t >> 5;       // 128 threads, 4 warps = 4 classes
    const float* hr = g_hid + (long)row * DH;
    float acc = 0.f;
    for (int k = lane; k < DH; k += 32) acc += hr[k] * W_cls[k * 4 + c];
    for (int o = 16; o; o >>= 1) acc += __shfl_xor_sync(0xffffffffu, acc, o);
    if (lane == 0) out[row * 4 + c] = acc + b_cls[c];
}

// ---------------- launcher ----------------
extern "C" void kernel_launch(void* const* d_in, const int* in_sizes, int n_in,
                              void* d_out, int out_size)
{
    const float* enc_img  = (const float*)d_in[0];
    const float* seq      = (const float*)d_in[1];
    const int*   starts   = (const int*)d_in[3];
    const int*   ends     = (const int*)d_in[4];
    const float* W_align  = (const float*)d_in[5];
    const float* b_align  = (const float*)d_in[6];
    const float* Wq       = (const float*)d_in[7];
    const float* Wk       = (const float*)d_in[8];
    const float* Wv       = (const float*)d_in[9];
    const float* Wfc      = (const float*)d_in[10];
    const float* ln_g     = (const float*)d_in[11];
    const float* ln_b     = (const float*)d_in[12];
    const float* W_a1     = (const float*)d_in[13];
    const float* b_a1     = (const float*)d_in[14];
    const float* W_a2     = (const float*)d_in[15];
    const float* b_a2     = (const float*)d_in[16];
    const float* W_un     = (const float*)d_in[17];
    const float* b_un     = (const float*)d_in[18];
    const float* W_dense  = (const float*)d_in[19];
    const float* b_dense  = (const float*)d_in[20];
    const float* W_cls    = (const float*)d_in[21];
    const float* b_cls    = (const float*)d_in[22];

    float *pC1, *pBqk, *pWvf, *pKC, *pVC, *pCat, *pF1, *pFused, *pPool, *pHid;
    cudaGetSymbolAddress((void**)&pC1, g_C1);
    cudaGetSymbolAddress((void**)&pBqk, g_Bqk);
    cudaGetSymbolAddress((void**)&pWvf, g_Wvf);
    cudaGetSymbolAddress((void**)&pKC, g_KC);
    cudaGetSymbolAddress((void**)&pVC, g_VC);
    cudaGetSymbolAddress((void**)&pCat, g_cat);
    cudaGetSymbolAddress((void**)&pF1, g_f1);
    cudaGetSymbolAddress((void**)&pFused, g_fused);
    cudaGetSymbolAddress((void**)&pPool, g_pool);
    cudaGetSymbolAddress((void**)&pHid, g_hid);

    const dim3 blk(256);
    const long HD2 = (long)DH * DH;      // 589824
    const long NRD = (long)NR * DH;      // 602112

    // res_feature = enc_img @ W_align + b_align            [784,768]
    sgemm<false, true, false><<<dim3(6, 7, 1), blk>>>(
        enc_img, IMGD, 0, W_align, DH, 0, pC1, DH, 0, b_align, NR, DH, IMGD);

    // Bqk_h = Wq_h @ Wk_h^T                                [8,768,768]
    sgemm<true, false, false><<<dim3(6, 6, HH), blk>>>(
        Wq, HH * DH, DH, Wk, HH * DH, DH, pBqk, DH, HD2, nullptr, DH, DH, DH);

    // Wvf_h = Wv_h @ Wfc_h                                 [8,768,768]
    sgemm<false, false, false><<<dim3(6, 6, HH), blk>>>(
        Wv, HH * DH, DH, Wfc, DH, HD2, pWvf, DH, HD2, nullptr, DH, DH, DH);

    // KC_h = C1 @ Bqk_h^T                                  [8,784,768]
    sgemm<true, false, false><<<dim3(6, 7, HH), blk>>>(
        pC1, DH, 0, pBqk, DH, HD2, pKC, DH, NRD, nullptr, NR, DH, DH);

    // VC_h = C1 @ Wvf_h                                    [8,784,768]
    sgemm<false, false, false><<<dim3(6, 7, HH), blk>>>(
        pC1, DH, 0, pWvf, DH, HD2, pVC, DH, NRD, nullptr, NR, DH, DH);

    // span gather
    gather_kernel<<<ROWS, 192>>>(seq, starts);

    // attention: scores + softmax, then out + residual
    att_scores_kernel<<<dim3(HH, NM), 256>>>();
    att_out_kernel<<<NM, 256>>>();
    ln_kernel<<<ROWS, 256>>>(ln_g, ln_b);

    // fusion MLP
    concat_kernel<<<ROWS, 192>>>();
    sgemm<false, true, true><<<dim3(12, 30, 1), blk>>>(
        pCat, 2 * DH, 0, W_a1, 2 * DH, 0, pF1, 2 * DH, 0, b_a1, ROWS, 2 * DH, 2 * DH);
    sgemm<false, true, false><<<dim3(6, 30, 1), blk>>>(
        pF1, 2 * DH, 0, W_a2, DH, 0, pFused, DH, 0, b_a2, ROWS, DH, 2 * DH);

    // pooling + head
    pool_kernel<<<NM, 256>>>(W_un, b_un, starts, ends);
    sgemm<false, true, true><<<dim3(6, 1, 1), blk>>>(
        pPool, DH, 0, W_dense, DH, 0, pHid, DH, 0, b_dense, NM, DH, DH);
    cls_kernel<<<NM, 128>>>(W_cls, b_cls, (float*)d_out);
}

// round 3
// speedup vs baseline: 1.6142x; 1.6142x over previous
#include <cuda_runtime.h>
#include <cuda_bf16.h>
#include <math.h>
#include <stdint.h>

// ---------------- problem constants ----------------
#define NB    16
#define LSEQ  128
#define DH    768
#define MSP   8
#define HH    8
#define JR    30
#define RR    49
#define IMGD  2048
#define NM    128            // NB*MSP
#define ROWS  3840           // NM*JR
#define NR    784            // NB*RR

typedef __nv_bfloat16 bf16;

// ---------------- scratch (device globals; no cudaMalloc allowed) ----------------
__device__ bf16 g_enc_hi[NR * IMGD],        g_enc_lo[NR * IMGD];
__device__ bf16 g_WalT_hi[DH * IMGD],       g_WalT_lo[DH * IMGD];
__device__ bf16 g_Wq_hi[DH * HH * DH],      g_Wq_lo[DH * HH * DH];
__device__ bf16 g_Wk_hi[DH * HH * DH],      g_Wk_lo[DH * HH * DH];
__device__ bf16 g_Wv_hi[DH * HH * DH],      g_Wv_lo[DH * HH * DH];
__device__ bf16 g_WfcT_hi[DH * HH * DH],    g_WfcT_lo[DH * HH * DH];
__device__ bf16 g_C1_hi[NR * DH],           g_C1_lo[NR * DH];
__device__ bf16 g_Bqk_hi[HH * DH * DH],     g_Bqk_lo[HH * DH * DH];
__device__ bf16 g_WvfT_hi[HH * DH * DH],    g_WvfT_lo[HH * DH * DH];
__device__ float g_KC[HH * NR * DH];
__device__ float g_VC[HH * NR * DH];
__device__ float g_span[ROWS * DH];
__device__ float g_att[ROWS * DH];
__device__ float g_P[NM * HH * JR * RR];
__device__ bf16 g_cat_hi[ROWS * 2 * DH],    g_cat_lo[ROWS * 2 * DH];
__device__ bf16 g_Wa1T_hi[2*DH * 2*DH],     g_Wa1T_lo[2*DH * 2*DH];
__device__ bf16 g_f1_hi[ROWS * 2 * DH],     g_f1_lo[ROWS * 2 * DH];
__device__ bf16 g_Wa2T_hi[DH * 2*DH],       g_Wa2T_lo[DH * 2*DH];
__device__ float g_fused[ROWS * DH];
__device__ float g_pool[NM * DH];
__device__ float g_hid[NM * DH];

// ---------------- warp-mma helpers ----------------
__device__ __forceinline__ uint32_t smem_u32(const void* p) {
    uint32_t a;
    asm("{ .reg .u64 t; cvta.to.shared.u64 t, %1; cvt.u32.u64 %0, t; }" : "=r"(a) : "l"(p));
    return a;
}

__device__ __forceinline__ void ldm_x4(uint32_t* r, uint32_t addr) {
    asm volatile("ldmatrix.sync.aligned.m8n8.x4.shared.b16 {%0,%1,%2,%3}, [%4];"
                 : "=r"(r[0]), "=r"(r[1]), "=r"(r[2]), "=r"(r[3]) : "r"(addr));
}

__device__ __forceinline__ void mma16816(float* c, const uint32_t* a, uint32_t b0, uint32_t b1) {
    asm volatile(
        "mma.sync.aligned.m16n8k16.row.col.f32.bf16.bf16.f32 "
        "{%0,%1,%2,%3}, {%4,%5,%6,%7}, {%8,%9}, {%0,%1,%2,%3};"
        : "+f"(c[0]), "+f"(c[1]), "+f"(c[2]), "+f"(c[3])
        : "r"(a[0]), "r"(a[1]), "r"(a[2]), "r"(a[3]), "r"(b0), "r"(b1));
}

// ---------------- split-bf16 tensor-core GEMM (HMMA path) ----------------
// C[M,N] = act( sum_k A[m,k]*B[n,k] + bias[n] ),  A,B as hi/lo bf16.
// Computes Ahi*Bhi + Ahi*Blo + Alo*Bhi (error ~2^-17, well under 1e-3 gate).
// Block 128x128, BK=32, 8 warps (2x4), warp tile 64x32, m16n8k16 fragments.
#define SPAD 40   // padded row length (bf16 elems): 80B rows, 16B aligned, ldmatrix conflict-free

template<bool OUT_BF16, bool BIAS, bool TANH_ACT>
__global__ __launch_bounds__(256, 2)
void mmgemm(const bf16* __restrict__ Ahi, const bf16* __restrict__ Alo, int lda, long sA,
            const bf16* __restrict__ Bhi, const bf16* __restrict__ Blo, int ldb, long sB,
            float* __restrict__ Cf, bf16* __restrict__ Chi, bf16* __restrict__ Clo,
            int ldc, long sC, const float* __restrict__ bias,
            int M, int N, int K)
{
    __shared__ bf16 sAh[128][SPAD], sAl[128][SPAD], sBh[128][SPAD], sBl[128][SPAD];

    Ahi += (long)blockIdx.z * sA;  Alo += (long)blockIdx.z * sA;
    Bhi += (long)blockIdx.z * sB;  Blo += (long)blockIdx.z * sB;
    const long coff = (long)blockIdx.z * sC;

    const int tid = threadIdx.x, lane = tid & 31, wid = tid >> 5;
    const int wr = wid >> 2, wc = wid & 3;              // warp row(2) x col(4)
    const int m0 = blockIdx.y * 128, n0 = blockIdx.x * 128;

    float acc[4][4][4];
#pragma unroll
    for (int i = 0; i < 4; i++)
#pragma unroll
        for (int j = 0; j < 4; j++)
#pragma unroll
            for (int e = 0; e < 4; e++) acc[i][j][e] = 0.f;

    // ldmatrix source addresses (per-thread constants modulo k offset)
    const int lrow = lane & 15, lcol = (lane >> 4) << 3;
    const uint32_t aAh = smem_u32(&sAh[wr * 64 + lrow][lcol]);
    const uint32_t aAl = smem_u32(&sAl[wr * 64 + lrow][lcol]);
    const uint32_t aBh = smem_u32(&sBh[wc * 32 + lrow][lcol]);
    const uint32_t aBl = smem_u32(&sBl[wc * 32 + lrow][lcol]);

    for (int k0 = 0; k0 < K; k0 += 32) {
        // cooperative tile loads: 128 rows x 32 bf16 per tile, float4 granularity
#pragma unroll
        for (int i = 0; i < 2; i++) {
            int u  = tid + i * 256;          // 0..511
            int r  = u >> 2;
            int sg = (u & 3) << 3;           // 0,8,16,24 bf16 elems
            int ga = m0 + r; if (ga > M - 1) ga = M - 1;
            int gb = n0 + r; if (gb > N - 1) gb = N - 1;
            *reinterpret_cast<float4*>(&sAh[r][sg]) =
                *reinterpret_cast<const float4*>(&Ahi[(long)ga * lda + k0 + sg]);
            *reinterpret_cast<float4*>(&sAl[r][sg]) =
                *reinterpret_cast<const float4*>(&Alo[(long)ga * lda + k0 + sg]);
            *reinterpret_cast<float4*>(&sBh[r][sg]) =
                *reinterpret_cast<const float4*>(&Bhi[(long)gb * ldb + k0 + sg]);
            *reinterpret_cast<float4*>(&sBl[r][sg]) =
                *reinterpret_cast<const float4*>(&Blo[(long)gb * ldb + k0 + sg]);
        }
        __syncthreads();

#pragma unroll
        for (int ks = 0; ks < 2; ks++) {
            const uint32_t ko = (uint32_t)(ks * 16 * sizeof(bf16));
            uint32_t bh[2][4], bl[2][4];
#pragma unroll
            for (int nt = 0; nt < 2; nt++) {
                ldm_x4(bh[nt], aBh + nt * (16 * SPAD * (int)sizeof(bf16)) + ko);
                ldm_x4(bl[nt], aBl + nt * (16 * SPAD * (int)sizeof(bf16)) + ko);
            }
#pragma unroll
            for (int mi = 0; mi < 4; mi++) {
                uint32_t ah[4], al[4];
                ldm_x4(ah, aAh + mi * (16 * SPAD * (int)sizeof(bf16)) + ko);
                ldm_x4(al, aAl + mi * (16 * SPAD * (int)sizeof(bf16)) + ko);
#pragma unroll
                for (int nt = 0; nt < 2; nt++) {
#pragma unroll
                    for (int j = 0; j < 2; j++) {
                        const int nj = nt * 2 + j;
                        mma16816(acc[mi][nj], ah, bh[nt][j], bh[nt][j + 2]);
                        mma16816(acc[mi][nj], ah, bl[nt][j], bl[nt][j + 2]);
                        mma16816(acc[mi][nj], al, bh[nt][j], bh[nt][j + 2]);
                    }
                }
            }
        }
        __syncthreads();
    }

    // epilogue: c0,c1 -> (row, col/col+1); c2,c3 -> (row+8, ...)
    const int ebase_r = m0 + wr * 64 + (lane >> 2);
    const int ebase_c = n0 + wc * 32 + (lane & 3) * 2;
#pragma unroll
    for (int mi = 0; mi < 4; mi++) {
#pragma unroll
        for (int nj = 0; nj < 4; nj++) {
            const int col = ebase_c + nj * 8;
            float bv0 = 0.f, bv1 = 0.f;
            if (BIAS) { bv0 = bias[col]; bv1 = bias[col + 1]; }
#pragma unroll
            for (int half = 0; half < 2; half++) {
                const int row = ebase_r + mi * 16 + half * 8;
                if (row >= M) continue;
                float v0 = acc[mi][nj][half * 2 + 0] + bv0;
                float v1 = acc[mi][nj][half * 2 + 1] + bv1;
                if (TANH_ACT) { v0 = tanhf(v0); v1 = tanhf(v1); }
                const long base = (long)row * ldc + coff + col;
                if (OUT_BF16) {
                    bf16 h0 = __float2bfloat16(v0);
                    bf16 h1 = __float2bfloat16(v1);
                    Chi[base] = h0;     Chi[base + 1] = h1;
                    Clo[base]     = __float2bfloat16(v0 - __bfloat162float(h0));
                    Clo[base + 1] = __float2bfloat16(v1 - __bfloat162float(h1));
                } else {
                    Cf[base] = v0;  Cf[base + 1] = v1;
                }
            }
        }
    }
}

// ---------------- fp32 -> bf16 hi/lo split (elementwise) ----------------
__global__ void split_kernel(const float* __restrict__ in, bf16* __restrict__ hi,
                             bf16* __restrict__ lo, long n)
{
    long i0 = ((long)blockIdx.x * blockDim.x + threadIdx.x) * 4;
    long stride = (long)gridDim.x * blockDim.x * 4;
    for (long i = i0; i < n; i += stride) {
        float4 v = *reinterpret_cast<const float4*>(in + i);
        float vv[4] = {v.x, v.y, v.z, v.w};
#pragma unroll
        for (int j = 0; j < 4; j++) {
            bf16 h = __float2bfloat16(vv[j]);
            hi[i + j] = h;
            lo[i + j] = __float2bfloat16(vv[j] - __bfloat162float(h));
        }
    }
}

// ---------------- fp32 [R,C] -> transposed bf16 hi/lo [C,R] ----------------
__global__ void splitT_kernel(const float* __restrict__ in, bf16* __restrict__ hi,
                              bf16* __restrict__ lo, int R, int C)
{
    __shared__ float t[32][33];
    int c0 = blockIdx.x * 32, r0 = blockIdx.y * 32;
    for (int i = threadIdx.y; i < 32; i += 8)
        t[i][threadIdx.x] = in[(long)(r0 + i) * C + c0 + threadIdx.x];
    __syncthreads();
    for (int i = threadIdx.y; i < 32; i += 8) {
        float v = t[threadIdx.x][i];
        long o = (long)(c0 + i) * R + r0 + threadIdx.x;
        bf16 h = __float2bfloat16(v);
        hi[o] = h;
        lo[o] = __float2bfloat16(v - __bfloat162float(h));
    }
}

// ---------------- concat(span, att) -> bf16 hi/lo ----------------
__global__ void concat_split_kernel()
{
    int row = blockIdx.x, t = threadIdx.x;
    for (int idx = t; idx < 2 * DH; idx += 256) {
        float v = (idx < DH) ? g_span[(long)row * DH + idx]
                             : g_att[(long)row * DH + idx - DH];
        long o = (long)row * 2 * DH + idx;
        bf16 h = __float2bfloat16(v);
        g_cat_hi[o] = h;
        g_cat_lo[o] = __float2bfloat16(v - __bfloat162float(h));
    }
}

// ---------------- span gather ----------------
__global__ void gather_kernel(const float* __restrict__ seq, const int* __restrict__ starts)
{
    int row = blockIdx.x;
    int sp = row / JR, j = row - sp * JR;
    int n = sp >> 3;
    int tok = starts[sp] + n * LSEQ + j;
    if (tok > NB * LSEQ - 1) tok = NB * LSEQ - 1;
    const float4* src = reinterpret_cast<const float4*>(seq + (long)tok * DH);
    float4* dst = reinterpret_cast<float4*>(g_span + (long)row * DH);
    int t = threadIdx.x;
    if (t < DH / 4) dst[t] = src[t];
}

// ---------------- attention scores + softmax (per span, head) ----------------
__global__ void att_scores_kernel()
{
    const int h = blockIdx.x, s = blockIdx.y;
    const int b = s >> 3;
    __shared__ float sQ[JR][129];
    __shared__ float sK[RR][129];
    __shared__ float sS[JR * RR];
    const int t = threadIdx.x;
    const int q = t % JR, rg = t / JR;

    int rr[7];
#pragma unroll
    for (int i = 0; i < 7; i++) { int r = rg + i * 8; rr[i] = (r < RR) ? r : 0; }
    float acc[7];
#pragma unroll
    for (int i = 0; i < 7; i++) acc[i] = 0.f;

    const float* Qp = g_span + (long)s * JR * DH;
    const float* Kp = g_KC + ((long)h * NR + (long)b * RR) * DH;

    for (int k0 = 0; k0 < DH; k0 += 128) {
        for (int e = t; e < JR * 128; e += 256)
            sQ[e >> 7][e & 127] = Qp[(long)(e >> 7) * DH + k0 + (e & 127)];
        for (int e = t; e < RR * 128; e += 256)
            sK[e >> 7][e & 127] = Kp[(long)(e >> 7) * DH + k0 + (e & 127)];
        __syncthreads();
        if (t < 240) {
            for (int kk = 0; kk < 128; kk++) {
                float a = sQ[q][kk];
#pragma unroll
                for (int i = 0; i < 7; i++) acc[i] += a * sK[rr[i]][kk];
            }
        }
        __syncthreads();
    }

    const float scale = 1.0f / sqrtf((float)DH);
    if (t < 240) {
#pragma unroll
        for (int i = 0; i < 7; i++) {
            int r = rg + i * 8;
            if (r < RR) sS[q * RR + r] = acc[i] * scale;
        }
    }
    __syncthreads();

    if (t < JR) {
        float* row = sS + t * RR;
        float mx = row[0];
        for (int r = 1; r < RR; r++) mx = fmaxf(mx, row[r]);
        float sum = 0.f;
        for (int r = 0; r < RR; r++) { float e = expf(row[r] - mx); row[r] = e; sum += e; }
        float inv = 1.f / sum;
        float* out = g_P + (((long)s * HH + h) * JR + t) * RR;
        for (int r = 0; r < RR; r++) out[r] = row[r] * inv;
    }
}

// ---------------- out = sum_h P_h @ VC_h + residual (per span) ----------------
__global__ void att_out_kernel()
{
    const int s = blockIdx.x, b = s >> 3, t = threadIdx.x;
    __shared__ float sP[HH * JR * RR];
    for (int e = t; e < HH * JR * RR; e += 256)
        sP[e] = g_P[(long)s * HH * JR * RR + e];
    __syncthreads();

    for (int dc = 0; dc < 3; dc++) {
        int d = dc * 256 + t;
        float acc[JR];
#pragma unroll
        for (int q = 0; q < JR; q++) acc[q] = 0.f;
        for (int h = 0; h < HH; h++) {
            const float* V = g_VC + ((long)h * NR + (long)b * RR) * DH + d;
            const float* P = sP + h * JR * RR;
            for (int r = 0; r < RR; r++) {
                float v = V[(long)r * DH];
#pragma unroll
                for (int q = 0; q < JR; q++) acc[q] += P[q * RR + r] * v;
            }
        }
        for (int q = 0; q < JR; q++) {
            long idx = ((long)s * JR + q) * DH + d;
            g_att[idx] = acc[q] + g_span[idx];
        }
    }
}

// ---------------- layernorm (in place on g_att) ----------------
__global__ void ln_kernel(const float* __restrict__ gam, const float* __restrict__ bet)
{
    int row = blockIdx.x, t = threadIdx.x;
    float* x = g_att + (long)row * DH;
    float v0 = x[t], v1 = x[t + 256], v2 = x[t + 512];
    __shared__ float red[256];
    red[t] = v0 + v1 + v2;
    __syncthreads();
    for (int o = 128; o > 0; o >>= 1) { if (t < o) red[t] += red[t + o]; __syncthreads(); }
    float mu = red[0] * (1.f / DH);
    __syncthreads();
    float d0 = v0 - mu, d1 = v1 - mu, d2 = v2 - mu;
    red[t] = d0 * d0 + d1 * d1 + d2 * d2;
    __syncthreads();
    for (int o = 128; o > 0; o >>= 1) { if (t < o) red[t] += red[t + o]; __syncthreads(); }
    float rstd = rsqrtf(red[0] * (1.f / DH) + 1e-5f);
    x[t]       = d0 * rstd * gam[t]       + bet[t];
    x[t + 256] = d1 * rstd * gam[t + 256] + bet[t + 256];
    x[t + 512] = d2 * rstd * gam[t + 512] + bet[t + 512];
}

// ---------------- unary score + masked softmax pooling ----------------
__global__ void pool_kernel(const float* __restrict__ W_un, const float* __restrict__ b_un,
                            const int* __restrict__ starts, const int* __restrict__ ends)
{
    int sp = blockIdx.x, t = threadIdx.x;
    int lane = t & 31, w = t >> 5;
    __shared__ float sS[JR];
    __shared__ float sProb[JR];

    for (int j = w; j < JR; j += 8) {
        const float* fr = g_fused + ((long)sp * JR + j) * DH;
        float acc = 0.f;
        for (int k = lane; k < DH; k += 32) acc += fr[k] * W_un[k];
        for (int o = 16; o; o >>= 1) acc += __shfl_xor_sync(0xffffffffu, acc, o);
        if (lane == 0) sS[j] = acc + b_un[0];
    }
    __syncthreads();
    if (t == 0) {
        int width = ends[sp] - starts[sp] + 1;
        float mx = -1e30f;
        for (int j = 0; j < JR; j++) {
            float v = sS[j] + ((j < width) ? 0.f : -10000.f);
            sS[j] = v; mx = fmaxf(mx, v);
        }
        float sum = 0.f;
        for (int j = 0; j < JR; j++) { float e = expf(sS[j] - mx); sProb[j] = e; sum += e; }
        float inv = 1.f / sum;
        for (int j = 0; j < JR; j++) sProb[j] *= inv;
    }
    __syncthreads();
    for (int d = t; d < DH; d += 256) {
        float acc = 0.f;
        for (int j = 0; j < JR; j++) acc += sProb[j] * g_fused[((long)sp * JR + j) * DH + d];
        g_pool[(long)sp * DH + d] = acc;
    }
}

// ---------------- small fp32 sgemm (tiny dense layer only) ----------------
template<bool TRANSB, bool BIAS, bool TANH_ACT>
__global__ void sgemm(const float* __restrict__ A, int lda, long sA,
                      const float* __restrict__ B, int ldb, long sB,
                      float* __restrict__ C, int ldc, long sC,
                      const float* __restrict__ bias,
                      int M, int N, int K)
{
    A += (long)blockIdx.z * sA;
    B += (long)blockIdx.z * sB;
    C += (long)blockIdx.z * sC;
    __shared__ float As[16][128];
    __shared__ float Bs[16][128];
    const int tid = threadIdx.x;
    const int m0 = blockIdx.y * 128;
    const int n0 = blockIdx.x * 128;
    const int tx = tid & 15;
    const int ty = tid >> 4;
    float acc[8][8];
#pragma unroll
    for (int i = 0; i < 8; i++)
#pragma unroll
        for (int j = 0; j < 8; j++) acc[i][j] = 0.f;

    for (int k0 = 0; k0 < K; k0 += 16) {
#pragma unroll
        for (int i = 0; i < 2; i++) {
            int li = tid + i * 256;
            int row = li >> 2;
            int kk  = (li & 3) << 2;
            float4 v = make_float4(0.f, 0.f, 0.f, 0.f);
            if (m0 + row < M)
                v = *reinterpret_cast<const float4*>(&A[(long)(m0 + row) * lda + k0 + kk]);
            As[kk + 0][row] = v.x; As[kk + 1][row] = v.y;
            As[kk + 2][row] = v.z; As[kk + 3][row] = v.w;
        }
        if (!TRANSB) {
#pragma unroll
            for (int i = 0; i < 2; i++) {
                int li = tid + i * 256;
                int kr = li >> 5;
                int nn = (li & 31) << 2;
                float4 v = *reinterpret_cast<const float4*>(&B[(long)(k0 + kr) * ldb + n0 + nn]);
                *reinterpret_cast<float4*>(&Bs[kr][nn]) = v;
            }
        } else {
#pragma unroll
            for (int i = 0; i < 2; i++) {
                int li = tid + i * 256;
                int nr = li >> 2;
                int kk = (li & 3) << 2;
                float4 v = make_float4(0.f, 0.f, 0.f, 0.f);
                if (n0 + nr < N)
                    v = *reinterpret_cast<const float4*>(&B[(long)(n0 + nr) * ldb + k0 + kk]);
                Bs[kk + 0][nr] = v.x; Bs[kk + 1][nr] = v.y;
                Bs[kk + 2][nr] = v.z; Bs[kk + 3][nr] = v.w;
            }
        }
        __syncthreads();
#pragma unroll
        for (int k = 0; k < 16; k++) {
            float a[8], b[8];
#pragma unroll
            for (int i = 0; i < 8; i++) a[i] = As[k][ty * 8 + i];
#pragma unroll
            for (int j = 0; j < 8; j++) b[j] = Bs[k][tx * 8 + j];
#pragma unroll
            for (int i = 0; i < 8; i++)
#pragma unroll
                for (int j = 0; j < 8; j++) acc[i][j] += a[i] * b[j];
        }
        __syncthreads();
    }
#pragma unroll
    for (int i = 0; i < 8; i++) {
        int m = m0 + ty * 8 + i;
        if (m >= M) continue;
#pragma unroll
        for (int j = 0; j < 8; j++) {
            int n = n0 + tx * 8 + j;
            float v = acc[i][j];
            if (BIAS) v += bias[n];
            if (TANH_ACT) v = tanhf(v);
            C[(long)m * ldc + n] = v;
        }
    }
}

// ---------------- classifier ----------------
__global__ void cls_kernel(const float* __restrict__ W_cls, const float* __restrict__ b_cls,
                           float* __restrict__ out)
{
    int row = blockIdx.x, t = threadIdx.x;
    int lane = t & 31, c = t >> 5;
    const float* hr = g_hid + (long)row * DH;
    float acc = 0.f;
    for (int k = lane; k < DH; k += 32) acc += hr[k] * W_cls[k * 4 + c];
    for (int o = 16; o; o >>= 1) acc += __shfl_xor_sync(0xffffffffu, acc, o);
    if (lane == 0) out[row * 4 + c] = acc + b_cls[c];
}

// ---------------- launcher ----------------
extern "C" void kernel_launch(void* const* d_in, const int* in_sizes, int n_in,
                              void* d_out, int out_size)
{
    const float* enc_img  = (const float*)d_in[0];
    const float* seq      = (const float*)d_in[1];
    const int*   starts   = (const int*)d_in[3];
    const int*   ends     = (const int*)d_in[4];
    const float* W_align  = (const float*)d_in[5];
    const float* b_align  = (const float*)d_in[6];
    const float* Wq       = (const float*)d_in[7];
    const float* Wk       = (const float*)d_in[8];
    const float* Wv       = (const float*)d_in[9];
    const float* Wfc      = (const float*)d_in[10];
    const float* ln_g     = (const float*)d_in[11];
    const float* ln_b     = (const float*)d_in[12];
    const float* W_a1     = (const float*)d_in[13];
    const float* b_a1     = (const float*)d_in[14];
    const float* W_a2     = (const float*)d_in[15];
    const float* b_a2     = (const float*)d_in[16];
    const float* W_un     = (const float*)d_in[17];
    const float* b_un     = (const float*)d_in[18];
    const float* W_dense  = (const float*)d_in[19];
    const float* b_dense  = (const float*)d_in[20];
    const float* W_cls    = (const float*)d_in[21];
    const float* b_cls    = (const float*)d_in[22];

    bf16 *eh, *el, *wath, *watl, *wqh, *wql, *wkh, *wkl, *wvh, *wvl, *wfh, *wfl;
    bf16 *c1h, *c1l, *bqh, *bql, *wvfh, *wvfl;
    bf16 *cth, *ctl, *wa1h, *wa1l, *f1h, *f1l, *wa2h, *wa2l;
    float *pKC, *pVC, *pFused, *pPool, *pHid;
    cudaGetSymbolAddress((void**)&eh,   g_enc_hi);  cudaGetSymbolAddress((void**)&el,   g_enc_lo);
    cudaGetSymbolAddress((void**)&wath, g_WalT_hi); cudaGetSymbolAddress((void**)&watl, g_WalT_lo);
    cudaGetSymbolAddress((void**)&wqh,  g_Wq_hi);   cudaGetSymbolAddress((void**)&wql,  g_Wq_lo);
    cudaGetSymbolAddress((void**)&wkh,  g_Wk_hi);   cudaGetSymbolAddress((void**)&wkl,  g_Wk_lo);
    cudaGetSymbolAddress((void**)&wvh,  g_Wv_hi);   cudaGetSymbolAddress((void**)&wvl,  g_Wv_lo);
    cudaGetSymbolAddress((void**)&wfh,  g_WfcT_hi); cudaGetSymbolAddress((void**)&wfl,  g_WfcT_lo);
    cudaGetSymbolAddress((void**)&c1h,  g_C1_hi);   cudaGetSymbolAddress((void**)&c1l,  g_C1_lo);
    cudaGetSymbolAddress((void**)&bqh,  g_Bqk_hi);  cudaGetSymbolAddress((void**)&bql,  g_Bqk_lo);
    cudaGetSymbolAddress((void**)&wvfh, g_WvfT_hi); cudaGetSymbolAddress((void**)&wvfl, g_WvfT_lo);
    cudaGetSymbolAddress((void**)&cth,  g_cat_hi);  cudaGetSymbolAddress((void**)&ctl,  g_cat_lo);
    cudaGetSymbolAddress((void**)&wa1h, g_Wa1T_hi); cudaGetSymbolAddress((void**)&wa1l, g_Wa1T_lo);
    cudaGetSymbolAddress((void**)&f1h,  g_f1_hi);   cudaGetSymbolAddress((void**)&f1l,  g_f1_lo);
    cudaGetSymbolAddress((void**)&wa2h, g_Wa2T_hi); cudaGetSymbolAddress((void**)&wa2l, g_Wa2T_lo);
    cudaGetSymbolAddress((void**)&pKC, g_KC);       cudaGetSymbolAddress((void**)&pVC, g_VC);
    cudaGetSymbolAddress((void**)&pFused, g_fused);
    cudaGetSymbolAddress((void**)&pPool, g_pool);   cudaGetSymbolAddress((void**)&pHid, g_hid);

    const dim3 blk(256);
    const long HD2 = (long)DH * DH;      // 589824
    const long NRD = (long)NR * DH;      // 602112

    // ---- operand conversions (fp32 -> bf16 hi/lo, transposed where needed) ----
    split_kernel<<<1024, 256>>>(enc_img, eh, el, (long)NR * IMGD);
    splitT_kernel<<<dim3(DH / 32, IMGD / 32), dim3(32, 8)>>>(W_align, wath, watl, IMGD, DH);
    split_kernel<<<1024, 256>>>(Wq, wqh, wql, (long)DH * HH * DH);
    split_kernel<<<1024, 256>>>(Wk, wkh, wkl, (long)DH * HH * DH);
    split_kernel<<<1024, 256>>>(Wv, wvh, wvl, (long)DH * HH * DH);
    splitT_kernel<<<dim3(DH / 32, (HH * DH) / 32), dim3(32, 8)>>>(Wfc, wfh, wfl, HH * DH, DH);
    splitT_kernel<<<dim3((2*DH) / 32, (2*DH) / 32), dim3(32, 8)>>>(W_a1, wa1h, wa1l, 2*DH, 2*DH);
    splitT_kernel<<<dim3(DH / 32, (2*DH) / 32), dim3(32, 8)>>>(W_a2, wa2h, wa2l, 2*DH, DH);

    // ---- G1: C1 = enc_img @ W_align + b_align -> bf16 hi/lo [784,768] ----
    mmgemm<true, true, false><<<dim3(6, 7, 1), blk>>>(
        eh, el, IMGD, 0, wath, watl, IMGD, 0,
        nullptr, c1h, c1l, DH, 0, b_align, NR, DH, IMGD);

    // ---- G2: Bqk_h = Wq_h @ Wk_h^T -> bf16 hi/lo [8][768,768] ----
    mmgemm<true, false, false><<<dim3(6, 6, HH), blk>>>(
        wqh, wql, HH * DH, DH, wkh, wkl, HH * DH, DH,
        nullptr, bqh, bql, DH, HD2, nullptr, DH, DH, DH);

    // ---- G3: WvfT_h = (Wv_h @ Wfc_h)^T -> bf16 hi/lo ----
    mmgemm<true, false, false><<<dim3(6, 6, HH), blk>>>(
        wfh, wfl, HH * DH, DH, wvh, wvl, HH * DH, DH,
        nullptr, wvfh, wvfl, DH, HD2, nullptr, DH, DH, DH);

    // ---- G4: KC_h = C1 @ Bqk_h^T -> fp32 [8][784,768] ----
    mmgemm<false, false, false><<<dim3(6, 7, HH), blk>>>(
        c1h, c1l, DH, 0, bqh, bql, DH, HD2,
        pKC, nullptr, nullptr, DH, NRD, nullptr, NR, DH, DH);

    // ---- G5: VC_h = C1 @ WvfT_h^T -> fp32 [8][784,768] ----
    mmgemm<false, false, false><<<dim3(6, 7, HH), blk>>>(
        c1h, c1l, DH, 0, wvfh, wvfl, DH, HD2,
        pVC, nullptr, nullptr, DH, NRD, nullptr, NR, DH, DH);

    // ---- span gather + attention + LN ----
    gather_kernel<<<ROWS, 192>>>(seq, starts);
    att_scores_kernel<<<dim3(HH, NM), 256>>>();
    att_out_kernel<<<NM, 256>>>();
    ln_kernel<<<ROWS, 256>>>(ln_g, ln_b);

    // ---- fusion MLP ----
    concat_split_kernel<<<ROWS, 256>>>();
    mmgemm<true, true, true><<<dim3(12, 30, 1), blk>>>(
        cth, ctl, 2 * DH, 0, wa1h, wa1l, 2 * DH, 0,
        nullptr, f1h, f1l, 2 * DH, 0, b_a1, ROWS, 2 * DH, 2 * DH);
    mmgemm<false, true, false><<<dim3(6, 30, 1), blk>>>(
        f1h, f1l, 2 * DH, 0, wa2h, wa2l, 2 * DH, 0,
        pFused, nullptr, nullptr, DH, 0, b_a2, ROWS, DH, 2 * DH);

    // ---- pooling + head ----
    pool_kernel<<<NM, 256>>>(W_un, b_un, starts, ends);
    sgemm<false, true, true><<<dim3(6, 1, 1), blk>>>(
        pPool, DH, 0, W_dense, DH, 0, pHid, DH, 0, b_dense, NM, DH, DH);
    cls_kernel<<<NM, 128>>>(W_cls, b_cls, (float*)d_out);
}